// round 1
// baseline (speedup 1.0000x reference)
#include <cuda_runtime.h>
#include <cstdint>

// Problem constants (from reference_code)
#define GS     256          // grid side (BOX * OS)
#define NCLS   10           // n_classes
#define NPTS   262144       // points per example (2^18)
#define BATCH  16
#define CELLS  (GS * GS)    // 65536

// ---------------------------------------------------------------------------
// Zero-fill the output image: BATCH*NCLS*CELLS = 10,485,760 floats = 2,621,440 float4
// ---------------------------------------------------------------------------
__global__ void zero_out_kernel(float4* __restrict__ out, int n4) {
    int i = blockIdx.x * blockDim.x + threadIdx.x;
    if (i < n4) out[i] = make_float4(0.f, 0.f, 0.f, 0.f);
}

// ---------------------------------------------------------------------------
// CIC scatter: one thread per point; loop over the 10 classes.
// points: [B, 2, N] float32, values: [B, NC, N] float32, out: [B, NC, GS*GS]
// ---------------------------------------------------------------------------
__global__ __launch_bounds__(256)
void cic_scatter_kernel(const float* __restrict__ points,
                        const float* __restrict__ values,
                        float* __restrict__ out) {
    const int gid = blockIdx.x * blockDim.x + threadIdx.x;  // 0 .. B*N-1
    const int b = gid >> 18;            // / NPTS
    const int n = gid & (NPTS - 1);     // % NPTS

    const float* pb = points + (size_t)b * 2 * NPTS;
    const float px = pb[n];
    const float py = pb[NPTS + n];

    // pixel coords in [0, 256)
    const float fx = (px + 0.5f) * (float)GS;
    const float fy = (py + 0.5f) * (float)GS;
    const float xf = floorf(fx);
    const float yf = floorf(fy);
    const float rx = fx - xf;
    const float ry = fy - yf;
    const int x = (int)xf;
    const int y = (int)yf;

    // x,y always in [0, 255]; only the +1 corners can fall off the grid
    const bool vx1 = (x + 1) < GS;
    const bool vy1 = (y + 1) < GS;

    const float wx0 = 1.f - rx, wx1 = rx;
    const float wy0 = 1.f - ry, wy1 = ry;
    const float w00 = wx0 * wy0;
    const float w10 = wx1 * wy0;
    const float w01 = wx0 * wy1;
    const float w11 = wx1 * wy1;

    const int i00 = y * GS + x;

    const float* vb = values + (size_t)b * NCLS * NPTS + n;
    float* ob = out + (size_t)b * NCLS * CELLS;

#pragma unroll
    for (int c = 0; c < NCLS; c++) {
        const float v = vb[(size_t)c * NPTS];      // coalesced across the warp
        float* o = ob + (size_t)c * CELLS;
        atomicAdd(o + i00, w00 * v);               // return unused -> RED
        if (vx1)        atomicAdd(o + i00 + 1,      w10 * v);
        if (vy1)        atomicAdd(o + i00 + GS,     w01 * v);
        if (vx1 && vy1) atomicAdd(o + i00 + GS + 1, w11 * v);
    }
}

// ---------------------------------------------------------------------------
// Harness entry point
// Inputs (metadata order): d_in[0] = points [16, 2, 262144] f32
//                          d_in[1] = values [16, 10, 262144] f32
// Output: d_out = [16, 10, 256, 256] f32
// ---------------------------------------------------------------------------
extern "C" void kernel_launch(void* const* d_in, const int* in_sizes, int n_in,
                              void* d_out, int out_size) {
    const float* points = (const float*)d_in[0];
    const float* values = (const float*)d_in[1];
    float* out = (float*)d_out;

    // 1) zero the output (poisoned by harness)
    const int n4 = (BATCH * NCLS * CELLS) / 4;          // 2,621,440
    zero_out_kernel<<<(n4 + 255) / 256, 256>>>((float4*)out, n4);

    // 2) scatter
    const int total = BATCH * NPTS;                      // 4,194,304
    cic_scatter_kernel<<<total / 256, 256>>>(points, values, out);
}

// round 2
// speedup vs baseline: 1.3624x; 1.3624x over previous
#include <cuda_runtime.h>
#include <cstdint>

#define GS     256
#define NCLS   10
#define NPTS   262144            // 2^18
#define BATCH  16
#define CELLS  (GS * GS)         // 65536
#define TCELLS (BATCH * CELLS)   // 1,048,576
#define PTOT   (BATCH * NPTS)    // 4,194,304
#define PAYF   12                // payload floats per point: v0..v9, rx, ry
#define IMGS   (BATCH * NCLS)    // 160

// ---------------------------------------------------------------------------
// Scratch (device globals: allocation-free per harness rules)
// ---------------------------------------------------------------------------
__device__ uint32_t g_hist[TCELLS];                       // per-(b,cell) counts
__device__ uint32_t g_base[TCELLS];                       // segment start (absolute)
__device__ uint32_t g_cursor[TCELLS];                     // scatter cursors
__device__ __align__(16) float g_payload[(size_t)PTOT * PAYF];      // ~201 MB
__device__ float g_S[4][(size_t)IMGS * CELLS];            // corner sums, [corner][b*NC+c][cell] ~168 MB

// ---------------------------------------------------------------------------
// Zero the histogram (must be re-zeroed on every launch for graph replay)
// ---------------------------------------------------------------------------
__global__ void zero_hist_kernel() {
    int i = blockIdx.x * blockDim.x + threadIdx.x;
    if (i < TCELLS) g_hist[i] = 0u;
}

// ---------------------------------------------------------------------------
// Shared coordinate math (must be bit-identical between hist and scatter)
// ---------------------------------------------------------------------------
__device__ __forceinline__ bool point_cell(const float* __restrict__ points,
                                           int b, int n,
                                           int& cell, float& rx, float& ry) {
    const float* pb = points + (size_t)b * 2 * NPTS;
    const float fx = (pb[n] + 0.5f) * (float)GS;
    const float fy = (pb[NPTS + n] + 0.5f) * (float)GS;
    const float xf = floorf(fx);
    const float yf = floorf(fy);
    const int x = (int)xf;
    const int y = (int)yf;
    rx = fx - xf;
    ry = fy - yf;
    cell = (y << 8) + x;
    // points with x or y outside [0,255] contribute nothing in the reference
    return ((unsigned)x < GS) && ((unsigned)y < GS);
}

// ---------------------------------------------------------------------------
// Pass A: histogram points per (batch, cell)
// ---------------------------------------------------------------------------
__global__ __launch_bounds__(256)
void hist_kernel(const float* __restrict__ points) {
    const int gid = blockIdx.x * blockDim.x + threadIdx.x;
    const int b = gid >> 18;
    const int n = gid & (NPTS - 1);
    int cell; float rx, ry;
    if (point_cell(points, b, n, cell, rx, ry))
        atomicAdd(&g_hist[(b << 16) + cell], 1u);
}

// ---------------------------------------------------------------------------
// Pass B: per-batch exclusive scan of 65536 counters (1 block per batch)
// 1024 threads x 64 elements each; Hillis-Steele block scan over partials.
// ---------------------------------------------------------------------------
__global__ __launch_bounds__(1024)
void scan_kernel() {
    const int b = blockIdx.x;
    const uint32_t* hist = g_hist + (size_t)b * CELLS;
    const int t = threadIdx.x;
    const int e0 = t * 64;

    uint32_t s = 0;
    for (int j = 0; j < 64; j++) s += hist[e0 + j];

    __shared__ uint32_t sm[1024];
    sm[t] = s;
    __syncthreads();
    for (int d = 1; d < 1024; d <<= 1) {
        uint32_t v = (t >= d) ? sm[t - d] : 0u;
        __syncthreads();
        sm[t] += v;
        __syncthreads();
    }
    uint32_t run = (uint32_t)b * NPTS + ((t == 0) ? 0u : sm[t - 1]);

    for (int j = 0; j < 64; j++) {
        const uint32_t h = hist[e0 + j];
        g_base[(size_t)b * CELLS + e0 + j]   = run;
        g_cursor[(size_t)b * CELLS + e0 + j] = run;
        run += h;
    }
}

// ---------------------------------------------------------------------------
// Pass C: scatter point payloads into per-cell segments
// ---------------------------------------------------------------------------
__global__ __launch_bounds__(256)
void scatter_kernel(const float* __restrict__ points,
                    const float* __restrict__ values) {
    const int gid = blockIdx.x * blockDim.x + threadIdx.x;
    const int b = gid >> 18;
    const int n = gid & (NPTS - 1);
    int cell; float rx, ry;
    if (!point_cell(points, b, n, cell, rx, ry)) return;

    const uint32_t pos = atomicAdd(&g_cursor[(b << 16) + cell], 1u);

    const float* vb = values + (size_t)b * NCLS * NPTS + n;
    float v[10];
#pragma unroll
    for (int c = 0; c < NCLS; c++) v[c] = vb[(size_t)c * NPTS];  // coalesced per class

    float4* dst = (float4*)(g_payload + (size_t)pos * PAYF);
    dst[0] = make_float4(v[0], v[1], v[2], v[3]);
    dst[1] = make_float4(v[4], v[5], v[6], v[7]);
    dst[2] = make_float4(v[8], v[9], rx, ry);
}

// ---------------------------------------------------------------------------
// Pass D: segmented reduce per (cell, class) -> 4 corner sums, no atomics.
// Block = 640 threads = 64 cells x 10 classes. Transposed coalesced writes.
// ---------------------------------------------------------------------------
__global__ __launch_bounds__(640)
void reduce_kernel() {
    const int t = threadIdx.x;
    const int cl = t / NCLS;          // 0..63 local cell
    const int c  = t - cl * NCLS;     // class
    const int cellg = blockIdx.x * 64 + cl;      // absolute (b,cell)

    const uint32_t start = g_base[cellg];
    const uint32_t cnt   = g_hist[cellg];

    float s00 = 0.f, s10 = 0.f, s01 = 0.f, s11 = 0.f;
    for (uint32_t i = 0; i < cnt; i++) {
        const float* p = g_payload + (size_t)(start + i) * PAYF;
        const float v  = p[c];
        const float rx = p[10];
        const float ry = p[11];
        const float wx0 = 1.f - rx, wy0 = 1.f - ry;
        s00 += wx0 * wy0 * v;
        s10 += rx  * wy0 * v;
        s01 += wx0 * ry  * v;
        s11 += rx  * ry  * v;
    }

    __shared__ float sm[4][640];
    sm[0][t] = s00; sm[1][t] = s10; sm[2][t] = s01; sm[3][t] = s11;
    __syncthreads();

    // transposed write: thread -> (class, local cell), coalesced over cells
    const int c2 = t / 64;            // class
    const int xl = t - c2 * 64;       // local cell
    const int cellbase = blockIdx.x * 64;
    const int b   = cellbase >> 16;
    const int cid = cellbase & (CELLS - 1);
    const size_t oidx = ((size_t)(b * NCLS + c2)) * CELLS + cid + xl;
#pragma unroll
    for (int k = 0; k < 4; k++)
        g_S[k][oidx] = sm[k][xl * NCLS + c2];
}

// ---------------------------------------------------------------------------
// Pass E: gather corner sums into the output (fully coalesced, writes all)
// out[b,c,Y,X] = S00(Y,X) + S10(Y,X-1) + S01(Y-1,X) + S11(Y-1,X-1)
// ---------------------------------------------------------------------------
__global__ __launch_bounds__(256)
void gather_kernel(float* __restrict__ out) {
    const int o = blockIdx.x * blockDim.x + threadIdx.x;   // 0..IMGS*CELLS
    const int idx = o & (CELLS - 1);
    const int X = idx & 255;
    const int Y = idx >> 8;
    const size_t base = (size_t)o;   // layout matches: [img][cell]

    float r = g_S[0][base];
    if (X > 0)          r += g_S[1][base - 1];
    if (Y > 0)          r += g_S[2][base - 256];
    if (X > 0 && Y > 0) r += g_S[3][base - 257];
    out[o] = r;
}

// ---------------------------------------------------------------------------
// Harness entry: d_in[0]=points [16,2,262144] f32, d_in[1]=values [16,10,262144] f32
// d_out = [16,10,256,256] f32
// ---------------------------------------------------------------------------
extern "C" void kernel_launch(void* const* d_in, const int* in_sizes, int n_in,
                              void* d_out, int out_size) {
    const float* points = (const float*)d_in[0];
    const float* values = (const float*)d_in[1];
    float* out = (float*)d_out;

    zero_hist_kernel<<<TCELLS / 256, 256>>>();
    hist_kernel<<<PTOT / 256, 256>>>(points);
    scan_kernel<<<BATCH, 1024>>>();
    scatter_kernel<<<PTOT / 256, 256>>>(points, values);
    reduce_kernel<<<TCELLS / 64, 640>>>();
    gather_kernel<<<(IMGS * CELLS) / 256, 256>>>(out);
}

// round 3
// speedup vs baseline: 1.5905x; 1.1674x over previous
#include <cuda_runtime.h>
#include <cstdint>

#define GS     256
#define NCLS   10
#define NPTS   262144            // 2^18
#define BATCH  16
#define CELLS  (GS * GS)         // 65536
#define TCELLS (BATCH * CELLS)   // 1,048,576
#define PTOT   (BATCH * NPTS)    // 4,194,304
#define PAYF   12                // payload floats per point: v0..v9, rx, ry
#define IMGS   (BATCH * NCLS)    // 160
#define OUTN   (IMGS * CELLS)    // 10,485,760 floats

// ---------------------------------------------------------------------------
// Scratch (device globals: allocation-free per harness rules)
// ---------------------------------------------------------------------------
__device__ uint32_t g_hist[TCELLS];                            // per-(b,cell) counts
__device__ uint32_t g_cursor[TCELLS];                          // scan bases -> scatter cursors -> segment ends
__device__ __align__(16) float g_payload[(size_t)PTOT * PAYF]; // ~201 MB
__device__ uint32_t g_bsum[1024];                              // scan block partials
__device__ uint32_t g_boff[1024];                              // scan block offsets

// ---------------------------------------------------------------------------
// Zero d_out (float4) + g_hist (uint4) in one kernel
// ---------------------------------------------------------------------------
#define OUT4  (OUTN / 4)       // 2,621,440
#define HIST4 (TCELLS / 4)     // 262,144
__global__ __launch_bounds__(256)
void zero_kernel(float4* __restrict__ out) {
    const int i = blockIdx.x * blockDim.x + threadIdx.x;
    if (i < OUT4) {
        out[i] = make_float4(0.f, 0.f, 0.f, 0.f);
    } else if (i < OUT4 + HIST4) {
        ((uint4*)g_hist)[i - OUT4] = make_uint4(0u, 0u, 0u, 0u);
    }
}

// ---------------------------------------------------------------------------
// Coordinate math (bit-identical between hist and scatter)
// ---------------------------------------------------------------------------
__device__ __forceinline__ bool point_cell(const float* __restrict__ points,
                                           int b, int n,
                                           int& cell, float& rx, float& ry) {
    const float* pb = points + (size_t)b * 2 * NPTS;
    const float fx = (pb[n] + 0.5f) * (float)GS;
    const float fy = (pb[NPTS + n] + 0.5f) * (float)GS;
    const float xf = floorf(fx);
    const float yf = floorf(fy);
    const int x = (int)xf;
    const int y = (int)yf;
    rx = fx - xf;
    ry = fy - yf;
    cell = (y << 8) + x;
    return ((unsigned)x < GS) && ((unsigned)y < GS);
}

// ---------------------------------------------------------------------------
// Pass A: histogram
// ---------------------------------------------------------------------------
__global__ __launch_bounds__(256)
void hist_kernel(const float* __restrict__ points) {
    const int gid = blockIdx.x * blockDim.x + threadIdx.x;
    const int b = gid >> 18;
    const int n = gid & (NPTS - 1);
    int cell; float rx, ry;
    if (point_cell(points, b, n, cell, rx, ry))
        atomicAdd(&g_hist[(b << 16) + cell], 1u);   // return unused -> RED
}

// ---------------------------------------------------------------------------
// Pass B: global exclusive scan of 1M counters (3 phases)
// ---------------------------------------------------------------------------
// B1: 1024 blocks x 256 thr, each block sums 1024 counters
__global__ __launch_bounds__(256)
void scan_partial_kernel() {
    const int t = threadIdx.x;
    const uint4 h = ((const uint4*)g_hist)[blockIdx.x * 256 + t];
    uint32_t s = h.x + h.y + h.z + h.w;
    __shared__ uint32_t sm[256];
    sm[t] = s;
    __syncthreads();
    for (int d = 128; d > 0; d >>= 1) {
        if (t < d) sm[t] += sm[t + d];
        __syncthreads();
    }
    if (t == 0) g_bsum[blockIdx.x] = sm[0];
}

// B2: 1 block x 1024 thr, exclusive scan of block sums
__global__ __launch_bounds__(1024)
void scan_top_kernel() {
    const int t = threadIdx.x;
    __shared__ uint32_t sm[1024];
    uint32_t v = g_bsum[t];
    sm[t] = v;
    __syncthreads();
    for (int d = 1; d < 1024; d <<= 1) {
        uint32_t u = (t >= d) ? sm[t - d] : 0u;
        __syncthreads();
        sm[t] += u;
        __syncthreads();
    }
    g_boff[t] = sm[t] - v;    // exclusive
}

// B3: 1024 blocks x 256 thr: local scan + block offset -> g_cursor
__global__ __launch_bounds__(256)
void scan_write_kernel() {
    const int t = threadIdx.x;
    const int idx = blockIdx.x * 256 + t;
    const uint4 h = ((const uint4*)g_hist)[idx];
    const uint32_t s = h.x + h.y + h.z + h.w;
    __shared__ uint32_t sm[256];
    sm[t] = s;
    __syncthreads();
    for (int d = 1; d < 256; d <<= 1) {
        uint32_t u = (t >= d) ? sm[t - d] : 0u;
        __syncthreads();
        sm[t] += u;
        __syncthreads();
    }
    uint32_t run = g_boff[blockIdx.x] + sm[t] - s;   // exclusive prefix for this thread
    uint4 c;
    c.x = run;                 run += h.x;
    c.y = run;                 run += h.y;
    c.z = run;                 run += h.z;
    c.w = run;
    ((uint4*)g_cursor)[idx] = c;
}

// ---------------------------------------------------------------------------
// Pass C: scatter point payloads into per-cell segments
// ---------------------------------------------------------------------------
__global__ __launch_bounds__(256)
void scatter_kernel(const float* __restrict__ points,
                    const float* __restrict__ values) {
    const int gid = blockIdx.x * blockDim.x + threadIdx.x;
    const int b = gid >> 18;
    const int n = gid & (NPTS - 1);
    int cell; float rx, ry;
    if (!point_cell(points, b, n, cell, rx, ry)) return;

    const uint32_t pos = atomicAdd(&g_cursor[(b << 16) + cell], 1u);

    const float* vb = values + (size_t)b * NCLS * NPTS + n;
    float v[10];
#pragma unroll
    for (int c = 0; c < NCLS; c++) v[c] = vb[(size_t)c * NPTS];

    float4* dst = (float4*)(g_payload + (size_t)pos * PAYF);
    dst[0] = make_float4(v[0], v[1], v[2], v[3]);
    dst[1] = make_float4(v[4], v[5], v[6], v[7]);
    dst[2] = make_float4(v[8], v[9], rx, ry);
}

// ---------------------------------------------------------------------------
// Pass D: fused reduce + corner-combine, direct to out.
// Block = 8x8 cell tile x 10 classes = 640 threads.
// Thread (c, ly, lx) reduces its cell segment into 4 corner sums, stages them
// in smem, then the block assembles the 9x9x10 output patch: interior
// positions are exclusive (plain store), the shared border frame uses
// atomicAdd into the pre-zeroed output.
// ---------------------------------------------------------------------------
__global__ __launch_bounds__(640)
void reduce_kernel(float* __restrict__ out) {
    const int t = threadIdx.x;
    const int c  = t >> 6;            // class 0..9
    const int cl = t & 63;            // local cell
    const int ly = cl >> 3;
    const int lx = cl & 7;

    const int blk = blockIdx.x;       // 0..16383
    const int b  = blk >> 10;
    const int tt = blk & 1023;
    const int ty = tt >> 5;           // tile row 0..31
    const int tx = tt & 31;           // tile col 0..31

    const int cellg = (b << 16) + ((ty * 8 + ly) << 8) + (tx * 8 + lx);
    const uint32_t cnt = g_hist[cellg];
    const uint32_t start = g_cursor[cellg] - cnt;    // cursor holds segment end

    float s00 = 0.f, s10 = 0.f, s01 = 0.f, s11 = 0.f;
    for (uint32_t i = 0; i < cnt; i++) {
        const float* p = g_payload + (size_t)(start + i) * PAYF;
        const float v  = p[c];
        const float rx = p[10];
        const float ry = p[11];
        const float wx0 = 1.f - rx, wy0 = 1.f - ry;
        s00 += wx0 * wy0 * v;
        s10 += rx  * wy0 * v;
        s01 += wx0 * ry  * v;
        s11 += rx  * ry  * v;
    }

    __shared__ float st[4][640];
    st[0][t] = s00; st[1][t] = s10; st[2][t] = s01; st[3][t] = s11;
    __syncthreads();

    // Assemble 9x9 patch per class: 810 outputs, 640 threads (<=2 each)
    for (int w = t; w < 810; w += 640) {
        const int c2 = w / 81;
        const int r  = w - 81 * c2;
        const int oy = r / 9;
        const int ox = r - 9 * oy;

        float v = 0.f;
        const int base = c2 << 6;
        if (oy < 8 && ox < 8)   v += st[0][base + oy * 8 + ox];
        if (oy < 8 && ox >= 1)  v += st[1][base + oy * 8 + ox - 1];
        if (oy >= 1 && ox < 8)  v += st[2][base + (oy - 1) * 8 + ox];
        if (oy >= 1 && ox >= 1) v += st[3][base + (oy - 1) * 8 + ox - 1];

        const int Y = ty * 8 + oy;
        const int X = tx * 8 + ox;
        if (Y > 255 || X > 255) continue;   // only possible for oy/ox == 8 at image edge

        float* dst = out + (((size_t)(b * NCLS + c2)) << 16) + (Y << 8) + X;
        const bool excl = (oy != 8) && (ox != 8) &&
                          (oy != 0 || ty == 0) && (ox != 0 || tx == 0);
        if (excl) *dst = v;
        else      atomicAdd(dst, v);
    }
}

// ---------------------------------------------------------------------------
// Harness entry: d_in[0]=points [16,2,262144] f32, d_in[1]=values [16,10,262144] f32
// d_out = [16,10,256,256] f32
// ---------------------------------------------------------------------------
extern "C" void kernel_launch(void* const* d_in, const int* in_sizes, int n_in,
                              void* d_out, int out_size) {
    const float* points = (const float*)d_in[0];
    const float* values = (const float*)d_in[1];
    float* out = (float*)d_out;

    zero_kernel<<<(OUT4 + HIST4 + 255) / 256, 256>>>((float4*)out);
    hist_kernel<<<PTOT / 256, 256>>>(points);
    scan_partial_kernel<<<1024, 256>>>();
    scan_top_kernel<<<1, 1024>>>();
    scan_write_kernel<<<1024, 256>>>();
    scatter_kernel<<<PTOT / 256, 256>>>(points, values);
    reduce_kernel<<<TCELLS / 64, 640>>>(out);
}

// round 4
// speedup vs baseline: 2.0469x; 1.2870x over previous
#include <cuda_runtime.h>
#include <cstdint>

#define GS     256
#define NCLS   10
#define NPTS   262144            // 2^18
#define BATCH  16
#define CELLS  (GS * GS)         // 65536
#define TCELLS (BATCH * CELLS)   // 1,048,576
#define PTOT   (BATCH * NPTS)    // 4,194,304
#define PAYF   16                // padded payload stride (floats): v0..v9, rx, ry, pad*4
#define IMGS   (BATCH * NCLS)    // 160
#define OUTN   (IMGS * CELLS)    // 10,485,760 floats

// ---------------------------------------------------------------------------
// Scratch (device globals: allocation-free per harness rules)
// ---------------------------------------------------------------------------
__device__ uint32_t g_hist[TCELLS];                            // per-(b,cell) counts
__device__ uint32_t g_cursor[TCELLS];                          // scan bases -> scatter cursors -> segment ends
__device__ __align__(16) float g_payload[(size_t)PTOT * PAYF]; // 268 MB, 64B-aligned records
__device__ uint32_t g_bsum[1024];
__device__ uint32_t g_boff[1024];

// ---------------------------------------------------------------------------
// Zero d_out (float4) + g_hist (uint4)
// ---------------------------------------------------------------------------
#define OUT4  (OUTN / 4)       // 2,621,440
#define HIST4 (TCELLS / 4)     // 262,144
__global__ __launch_bounds__(256)
void zero_kernel(float4* __restrict__ out) {
    const int i = blockIdx.x * blockDim.x + threadIdx.x;
    if (i < OUT4) {
        out[i] = make_float4(0.f, 0.f, 0.f, 0.f);
    } else if (i < OUT4 + HIST4) {
        ((uint4*)g_hist)[i - OUT4] = make_uint4(0u, 0u, 0u, 0u);
    }
}

// ---------------------------------------------------------------------------
// Coordinate math (bit-identical between hist and scatter)
// ---------------------------------------------------------------------------
__device__ __forceinline__ bool point_cell(const float* __restrict__ points,
                                           int b, int n,
                                           int& cell, float& rx, float& ry) {
    const float* pb = points + (size_t)b * 2 * NPTS;
    const float fx = (pb[n] + 0.5f) * (float)GS;
    const float fy = (pb[NPTS + n] + 0.5f) * (float)GS;
    const float xf = floorf(fx);
    const float yf = floorf(fy);
    const int x = (int)xf;
    const int y = (int)yf;
    rx = fx - xf;
    ry = fy - yf;
    cell = (y << 8) + x;
    return ((unsigned)x < GS) && ((unsigned)y < GS);
}

// ---------------------------------------------------------------------------
// Pass A: histogram
// ---------------------------------------------------------------------------
__global__ __launch_bounds__(256)
void hist_kernel(const float* __restrict__ points) {
    const int gid = blockIdx.x * blockDim.x + threadIdx.x;
    const int b = gid >> 18;
    const int n = gid & (NPTS - 1);
    int cell; float rx, ry;
    if (point_cell(points, b, n, cell, rx, ry))
        atomicAdd(&g_hist[(b << 16) + cell], 1u);
}

// ---------------------------------------------------------------------------
// Pass B: global exclusive scan of 1M counters (3 phases)
// ---------------------------------------------------------------------------
__global__ __launch_bounds__(256)
void scan_partial_kernel() {
    const int t = threadIdx.x;
    const uint4 h = ((const uint4*)g_hist)[blockIdx.x * 256 + t];
    uint32_t s = h.x + h.y + h.z + h.w;
    __shared__ uint32_t sm[256];
    sm[t] = s;
    __syncthreads();
    for (int d = 128; d > 0; d >>= 1) {
        if (t < d) sm[t] += sm[t + d];
        __syncthreads();
    }
    if (t == 0) g_bsum[blockIdx.x] = sm[0];
}

__global__ __launch_bounds__(1024)
void scan_top_kernel() {
    const int t = threadIdx.x;
    __shared__ uint32_t sm[1024];
    uint32_t v = g_bsum[t];
    sm[t] = v;
    __syncthreads();
    for (int d = 1; d < 1024; d <<= 1) {
        uint32_t u = (t >= d) ? sm[t - d] : 0u;
        __syncthreads();
        sm[t] += u;
        __syncthreads();
    }
    g_boff[t] = sm[t] - v;
}

__global__ __launch_bounds__(256)
void scan_write_kernel() {
    const int t = threadIdx.x;
    const int idx = blockIdx.x * 256 + t;
    const uint4 h = ((const uint4*)g_hist)[idx];
    const uint32_t s = h.x + h.y + h.z + h.w;
    __shared__ uint32_t sm[256];
    sm[t] = s;
    __syncthreads();
    for (int d = 1; d < 256; d <<= 1) {
        uint32_t u = (t >= d) ? sm[t - d] : 0u;
        __syncthreads();
        sm[t] += u;
        __syncthreads();
    }
    uint32_t run = g_boff[blockIdx.x] + sm[t] - s;
    uint4 c;
    c.x = run;  run += h.x;
    c.y = run;  run += h.y;
    c.z = run;  run += h.z;
    c.w = run;
    ((uint4*)g_cursor)[idx] = c;
}

// ---------------------------------------------------------------------------
// Pass C: scatter point payloads into per-cell segments (64B-aligned records)
// ---------------------------------------------------------------------------
__global__ __launch_bounds__(256)
void scatter_kernel(const float* __restrict__ points,
                    const float* __restrict__ values) {
    const int gid = blockIdx.x * blockDim.x + threadIdx.x;
    const int b = gid >> 18;
    const int n = gid & (NPTS - 1);
    int cell; float rx, ry;
    if (!point_cell(points, b, n, cell, rx, ry)) return;

    const uint32_t pos = atomicAdd(&g_cursor[(b << 16) + cell], 1u);

    const float* vb = values + (size_t)b * NCLS * NPTS + n;
    float v[10];
#pragma unroll
    for (int c = 0; c < NCLS; c++) v[c] = vb[(size_t)c * NPTS];

    float4* dst = (float4*)(g_payload + ((size_t)pos << 4));
    dst[0] = make_float4(v[0], v[1], v[2], v[3]);
    dst[1] = make_float4(v[4], v[5], v[6], v[7]);
    dst[2] = make_float4(v[8], v[9], rx, ry);
}

// ---------------------------------------------------------------------------
// Pass D: fused reduce + corner-combine, one THREAD per CELL.
// Block = 16x16 cell tile, 256 threads. Each thread keeps 4x10 accumulators
// in registers, reads each record once as 3x LDG.128. Corner sums staged in
// smem, then the block assembles the 17x17x10 output patch.
// ---------------------------------------------------------------------------
__global__ __launch_bounds__(256)
void reduce_kernel(float* __restrict__ out) {
    const int t = threadIdx.x;
    const int ly = t >> 4;
    const int lx = t & 15;

    const int blk = blockIdx.x;        // 0..4095
    const int b  = blk >> 8;           // batch
    const int tt = blk & 255;
    const int ty = tt >> 4;            // tile row 0..15
    const int tx = tt & 15;            // tile col 0..15

    const int cellg = (b << 16) + ((ty * 16 + ly) << 8) + (tx * 16 + lx);
    const uint32_t cnt = g_hist[cellg];
    const uint32_t start = g_cursor[cellg] - cnt;   // cursor holds segment end

    float acc[4][NCLS];
#pragma unroll
    for (int k = 0; k < 4; k++)
#pragma unroll
        for (int c = 0; c < NCLS; c++) acc[k][c] = 0.f;

    const float4* pay = (const float4*)g_payload;
    for (uint32_t i = 0; i < cnt; i++) {
        const size_t r4 = ((size_t)(start + i)) << 2;   // float4 index (stride 4)
        const float4 a = __ldg(pay + r4 + 0);
        const float4 bq = __ldg(pay + r4 + 1);
        const float4 cq = __ldg(pay + r4 + 2);
        const float rx = cq.z, ry = cq.w;
        const float wx0 = 1.f - rx, wy0 = 1.f - ry;
        const float w00 = wx0 * wy0, w10 = rx * wy0, w01 = wx0 * ry, w11 = rx * ry;
        float v[10] = {a.x, a.y, a.z, a.w, bq.x, bq.y, bq.z, bq.w, cq.x, cq.y};
#pragma unroll
        for (int c = 0; c < NCLS; c++) {
            acc[0][c] += w00 * v[c];
            acc[1][c] += w10 * v[c];
            acc[2][c] += w01 * v[c];
            acc[3][c] += w11 * v[c];
        }
    }

    // stage: st[corner][class][cell]  (stride-1 in cell -> conflict-free)
    __shared__ float st[4][NCLS][256];
#pragma unroll
    for (int k = 0; k < 4; k++)
#pragma unroll
        for (int c = 0; c < NCLS; c++) st[k][c][t] = acc[k][c];
    __syncthreads();

    // assemble 17x17 patch per class: 2890 outputs over 256 threads
    for (int w = t; w < 17 * 17 * NCLS; w += 256) {
        const int c2 = w / 289;
        const int r  = w - 289 * c2;
        const int oy = r / 17;
        const int ox = r - 17 * oy;

        float v = 0.f;
        if (oy < 16 && ox < 16)   v += st[0][c2][oy * 16 + ox];
        if (oy < 16 && ox >= 1)   v += st[1][c2][oy * 16 + ox - 1];
        if (oy >= 1 && ox < 16)   v += st[2][c2][(oy - 1) * 16 + ox];
        if (oy >= 1 && ox >= 1)   v += st[3][c2][(oy - 1) * 16 + ox - 1];

        const int Y = ty * 16 + oy;
        const int X = tx * 16 + ox;
        if (Y > 255 || X > 255) continue;

        float* dst = out + (((size_t)(b * NCLS + c2)) << 16) + (Y << 8) + X;
        const bool excl = (oy != 16) && (ox != 16) &&
                          (oy != 0 || ty == 0) && (ox != 0 || tx == 0);
        if (excl) *dst = v;
        else      atomicAdd(dst, v);
    }
}

// ---------------------------------------------------------------------------
// Harness entry: d_in[0]=points [16,2,262144] f32, d_in[1]=values [16,10,262144] f32
// d_out = [16,10,256,256] f32
// ---------------------------------------------------------------------------
extern "C" void kernel_launch(void* const* d_in, const int* in_sizes, int n_in,
                              void* d_out, int out_size) {
    const float* points = (const float*)d_in[0];
    const float* values = (const float*)d_in[1];
    float* out = (float*)d_out;

    zero_kernel<<<(OUT4 + HIST4 + 255) / 256, 256>>>((float4*)out);
    hist_kernel<<<PTOT / 256, 256>>>(points);
    scan_partial_kernel<<<1024, 256>>>();
    scan_top_kernel<<<1, 1024>>>();
    scan_write_kernel<<<1024, 256>>>();
    scatter_kernel<<<PTOT / 256, 256>>>(points, values);
    reduce_kernel<<<TCELLS / 256, 256>>>(out);
}

// round 5
// speedup vs baseline: 2.1825x; 1.0663x over previous
#include <cuda_runtime.h>
#include <cstdint>

#define GS     256
#define NCLS   10
#define NPTS   262144            // 2^18
#define BATCH  16
#define CELLS  (GS * GS)         // 65536
#define TCELLS (BATCH * CELLS)   // 1,048,576
#define PTOT   (BATCH * NPTS)    // 4,194,304
#define CAP    16                // bucket capacity per cell (Poisson(4): P(>16) ~ 1e-6)
#define PAYF   12                // 48B record: v0..v9, rx, ry
#define IMGS   (BATCH * NCLS)    // 160
#define OUTN   (IMGS * CELLS)    // 10,485,760 floats

// ---------------------------------------------------------------------------
// Scratch (device globals: allocation-free per harness rules)
// ---------------------------------------------------------------------------
__device__ uint32_t g_cursor[TCELLS];                               // per-cell fill counters
__device__ __align__(16) float g_payload[(size_t)TCELLS * CAP * PAYF];  // 768 MB bucket store

// ---------------------------------------------------------------------------
// Zero d_out (float4) + g_cursor (uint4)
// ---------------------------------------------------------------------------
#define OUT4  (OUTN / 4)       // 2,621,440
#define CUR4  (TCELLS / 4)     // 262,144
__global__ __launch_bounds__(256)
void zero_kernel(float4* __restrict__ out) {
    const int i = blockIdx.x * blockDim.x + threadIdx.x;
    if (i < OUT4) {
        out[i] = make_float4(0.f, 0.f, 0.f, 0.f);
    } else if (i < OUT4 + CUR4) {
        ((uint4*)g_cursor)[i - OUT4] = make_uint4(0u, 0u, 0u, 0u);
    }
}

// ---------------------------------------------------------------------------
// Pass A: scatter into fixed-capacity buckets; rare overflow -> direct atomics
// ---------------------------------------------------------------------------
__global__ __launch_bounds__(256)
void scatter_kernel(const float* __restrict__ points,
                    const float* __restrict__ values,
                    float* __restrict__ out) {
    const int gid = blockIdx.x * blockDim.x + threadIdx.x;
    const int b = gid >> 18;
    const int n = gid & (NPTS - 1);

    const float* pb = points + (size_t)b * 2 * NPTS;
    const float fx = (pb[n] + 0.5f) * (float)GS;
    const float fy = (pb[NPTS + n] + 0.5f) * (float)GS;
    const float xf = floorf(fx);
    const float yf = floorf(fy);
    const int x = (int)xf;
    const int y = (int)yf;
    const float rx = fx - xf;
    const float ry = fy - yf;
    if (((unsigned)x >= GS) || ((unsigned)y >= GS)) return;  // contributes nothing

    const int cellg = (b << 16) + (y << 8) + x;
    const uint32_t slot = atomicAdd(&g_cursor[cellg], 1u);

    const float* vb = values + (size_t)b * NCLS * NPTS + n;
    float v[10];
#pragma unroll
    for (int c = 0; c < NCLS; c++) v[c] = vb[(size_t)c * NPTS];  // coalesced per class

    if (slot < CAP) {
        float4* dst = (float4*)(g_payload + ((size_t)cellg * CAP + slot) * PAYF);
        __stcs(dst + 0, make_float4(v[0], v[1], v[2], v[3]));
        __stcs(dst + 1, make_float4(v[4], v[5], v[6], v[7]));
        __stcs(dst + 2, make_float4(v[8], v[9], rx, ry));
    } else {
        // overflow (expected ~a few points per run): direct CIC atomics into out
        const bool vx1 = (x + 1) < GS;
        const bool vy1 = (y + 1) < GS;
        const float wx0 = 1.f - rx, wy0 = 1.f - ry;
        const float w00 = wx0 * wy0, w10 = rx * wy0, w01 = wx0 * ry, w11 = rx * ry;
        const int i00 = (y << 8) + x;
        float* ob = out + (size_t)b * NCLS * CELLS;
#pragma unroll
        for (int c = 0; c < NCLS; c++) {
            float* o = ob + ((size_t)c << 16);
            atomicAdd(o + i00, w00 * v[c]);
            if (vx1)        atomicAdd(o + i00 + 1,      w10 * v[c]);
            if (vy1)        atomicAdd(o + i00 + GS,     w01 * v[c]);
            if (vx1 && vy1) atomicAdd(o + i00 + GS + 1, w11 * v[c]);
        }
    }
}

// ---------------------------------------------------------------------------
// Pass B: fused reduce + corner-combine, one THREAD per CELL.
// Block = 16x16 cell tile, 256 threads, 40 register accumulators per thread.
// Interior patch positions: non-atomic read-modify-write (preserves overflow
// atomics already in out). Shared border frame: atomicAdd.
// ---------------------------------------------------------------------------
__global__ __launch_bounds__(256)
void reduce_kernel(float* __restrict__ out) {
    const int t = threadIdx.x;
    const int ly = t >> 4;
    const int lx = t & 15;

    const int blk = blockIdx.x;        // 0..4095
    const int b  = blk >> 8;
    const int tt = blk & 255;
    const int ty = tt >> 4;            // tile row 0..15
    const int tx = tt & 15;            // tile col 0..15

    const int cellg = (b << 16) + ((ty * 16 + ly) << 8) + (tx * 16 + lx);
    const uint32_t raw = g_cursor[cellg];
    const uint32_t cnt = raw < CAP ? raw : CAP;

    float acc[4][NCLS];
#pragma unroll
    for (int k = 0; k < 4; k++)
#pragma unroll
        for (int c = 0; c < NCLS; c++) acc[k][c] = 0.f;

    const float4* pay = (const float4*)g_payload;
    const size_t base4 = (size_t)cellg * CAP * 3;       // float4 units, 3 per record
    for (uint32_t i = 0; i < cnt; i++) {
        const size_t r4 = base4 + (size_t)i * 3;
        const float4 a  = __ldcs(pay + r4 + 0);
        const float4 bq = __ldcs(pay + r4 + 1);
        const float4 cq = __ldcs(pay + r4 + 2);
        const float rx = cq.z, ry = cq.w;
        const float wx0 = 1.f - rx, wy0 = 1.f - ry;
        const float w00 = wx0 * wy0, w10 = rx * wy0, w01 = wx0 * ry, w11 = rx * ry;
        const float v[10] = {a.x, a.y, a.z, a.w, bq.x, bq.y, bq.z, bq.w, cq.x, cq.y};
#pragma unroll
        for (int c = 0; c < NCLS; c++) {
            acc[0][c] += w00 * v[c];
            acc[1][c] += w10 * v[c];
            acc[2][c] += w01 * v[c];
            acc[3][c] += w11 * v[c];
        }
    }

    // stage: st[corner][class][cell] (stride-1 in cell -> conflict-free)
    __shared__ float st[4][NCLS][256];
#pragma unroll
    for (int k = 0; k < 4; k++)
#pragma unroll
        for (int c = 0; c < NCLS; c++) st[k][c][t] = acc[k][c];
    __syncthreads();

    // assemble 17x17 patch per class: 2890 outputs over 256 threads
    for (int w = t; w < 17 * 17 * NCLS; w += 256) {
        const int c2 = w / 289;
        const int r  = w - 289 * c2;
        const int oy = r / 17;
        const int ox = r - 17 * oy;

        float v = 0.f;
        if (oy < 16 && ox < 16)   v += st[0][c2][oy * 16 + ox];
        if (oy < 16 && ox >= 1)   v += st[1][c2][oy * 16 + ox - 1];
        if (oy >= 1 && ox < 16)   v += st[2][c2][(oy - 1) * 16 + ox];
        if (oy >= 1 && ox >= 1)   v += st[3][c2][(oy - 1) * 16 + ox - 1];

        const int Y = ty * 16 + oy;
        const int X = tx * 16 + ox;
        if (Y > 255 || X > 255) continue;

        float* dst = out + (((size_t)(b * NCLS + c2)) << 16) + (Y << 8) + X;
        const bool excl = (oy != 16) && (ox != 16) &&
                          (oy != 0 || ty == 0) && (ox != 0 || tx == 0);
        if (excl) *dst = v + *dst;      // plain RMW keeps overflow contributions
        else      atomicAdd(dst, v);
    }
}

// ---------------------------------------------------------------------------
// Harness entry: d_in[0]=points [16,2,262144] f32, d_in[1]=values [16,10,262144] f32
// d_out = [16,10,256,256] f32
// ---------------------------------------------------------------------------
extern "C" void kernel_launch(void* const* d_in, const int* in_sizes, int n_in,
                              void* d_out, int out_size) {
    const float* points = (const float*)d_in[0];
    const float* values = (const float*)d_in[1];
    float* out = (float*)d_out;

    zero_kernel<<<(OUT4 + CUR4 + 255) / 256, 256>>>((float4*)out);
    scatter_kernel<<<PTOT / 256, 256>>>(points, values, out);
    reduce_kernel<<<TCELLS / 256, 256>>>(out);
}